// round 13
// baseline (speedup 1.0000x reference)
#include <cuda_runtime.h>
#include <cuda_bf16.h>
#include <math.h>

// Problem constants
#define B 4
#define T 512
#define C 256
#define C2 512
#define HEADS 4
#define MAXOFF 2
#define M (B * T)      // 2048

#define TI 32          // i-tile per block (rep)
#define TJ 64          // j-tile per block (rep)
#define NJT (T / TJ)   // 8 j-tiles
#define CK 64          // c chunk (rep)

typedef unsigned long long u64;

// Scratch (allocation-free: device globals)
__device__ float g_subjT[C * M];                // [c][m] transposed
__device__ float g_objT[C * M];
__device__ float g_part[M * NJT * HEADS];       // partial exp-sums per j-tile
__device__ float g_swow[2 * M * HEADS];         // Sw rows 0..M-1, Ow rows M..

// packed f32x2 helpers
static __device__ __forceinline__ u64 fma2(u64 a, u64 b, u64 c) {
    u64 r; asm("fma.rn.f32x2 %0, %1, %2, %3;" : "=l"(r) : "l"(a), "l"(b), "l"(c)); return r;
}
static __device__ __forceinline__ float2 unpack2(u64 v) {
    float2 r; asm("mov.b64 {%0, %1}, %2;" : "=f"(r.x), "=f"(r.y) : "l"(v)); return r;
}
static __device__ __forceinline__ u64 pack2(float lo, float hi) {
    u64 r; asm("mov.b64 %0, {%1, %2};" : "=l"(r) : "f"(lo), "f"(hi)); return r;
}
// packed min (FMNMX on ALU pipe)
static __device__ __forceinline__ u64 fmin2(u64 a, u64 b) {
    union { u64 v; float2 f; } ua, ub, uc;
    ua.v = a; ub.v = b;
    uc.f.x = fminf(ua.f.x, ub.f.x);
    uc.f.y = fminf(ua.f.y, ub.f.y);
    return uc.v;
}

// ---------------------------------------------------------------------------
// Kernel 1: max-pool along channel (window 5, pad 2) + concat -> x_new
// ---------------------------------------------------------------------------
__global__ void pool_concat_kernel(const float* __restrict__ x,
                                   float* __restrict__ xnew) {
    int idx = blockIdx.x * 256 + threadIdx.x;
    if (idx >= M * C2) return;
    int cc = idx & (C2 - 1);
    int bt = idx >> 9;
    const float* xr = x + bt * C;
    float v;
    if (cc < C) {
        int lo = cc - MAXOFF; if (lo < 0) lo = 0;
        int hi = cc + MAXOFF; if (hi > C - 1) hi = C - 1;
        v = -INFINITY;
        #pragma unroll 5
        for (int c = lo; c <= hi; c++) v = fmaxf(v, xr[c]);
    } else {
        v = xr[cc - C];
    }
    xnew[idx] = v;
}

// ---------------------------------------------------------------------------
// Kernel 2: projection GEMMs, m-packed f32x2 (R11 core); TRANSPOSED-only out.
// Tile 64m x 64n, 128 threads (tx 0..15 = n-quad, ty 0..7 = m-octet).
// ---------------------------------------------------------------------------
__global__ void __launch_bounds__(128)
gemm_kernel(const float* __restrict__ A,
            const float* __restrict__ W0,
            const float* __restrict__ b0,
            const float* __restrict__ W1,
            const float* __restrict__ b1,
            float* __restrict__ outT0,
            float* __restrict__ outT1) {
    __shared__ float As[16 * 68];   // [k][m], stride 68
    __shared__ float Ws[16 * 68];   // [k][n], stride 68

    const float* W    = blockIdx.z ? W1 : W0;
    const float* bias = blockIdx.z ? b1 : b0;
    float* outT       = blockIdx.z ? outT1 : outT0;

    const int tid = threadIdx.x;
    const int tx = tid & 15;           // n quad: n = 4tx..4tx+3
    const int ty = tid >> 4;           // m octet: m = 8ty..8ty+7
    const int bm = blockIdx.y * 64;
    const int bn = blockIdx.x * 64;

    u64 acc[4][4];
    #pragma unroll
    for (int p = 0; p < 4; p++)
        #pragma unroll
        for (int n = 0; n < 4; n++) acc[p][n] = 0ULL;

    for (int k0 = 0; k0 < C2; k0 += 16) {
        #pragma unroll
        for (int l = 0; l < 2; l++) {
            int idx = tid + l * 128;
            int m = idx >> 2, kq = idx & 3;
            float4 av = *(const float4*)&A[(bm + m) * C2 + k0 + 4 * kq];
            As[(4 * kq + 0) * 68 + m] = av.x;
            As[(4 * kq + 1) * 68 + m] = av.y;
            As[(4 * kq + 2) * 68 + m] = av.z;
            As[(4 * kq + 3) * 68 + m] = av.w;
        }
        #pragma unroll
        for (int l = 0; l < 2; l++) {
            int idx = tid + l * 128;
            int nq = idx & 15, kw = idx >> 4;
            float4 wv = *(const float4*)&W[(k0 + kw) * C + bn + 4 * nq];
            *(float4*)&Ws[kw * 68 + 4 * nq] = wv;
        }
        __syncthreads();

        #pragma unroll
        for (int k = 0; k < 16; k++) {
            ulonglong2 A01 = *(const ulonglong2*)&As[k * 68 + 8 * ty];
            ulonglong2 A23 = *(const ulonglong2*)&As[k * 68 + 8 * ty + 4];
            float4 wv = *(const float4*)&Ws[k * 68 + 4 * tx];
            u64 wd[4];
            wd[0] = pack2(wv.x, wv.x);
            wd[1] = pack2(wv.y, wv.y);
            wd[2] = pack2(wv.z, wv.z);
            wd[3] = pack2(wv.w, wv.w);
            u64 ap[4] = {A01.x, A01.y, A23.x, A23.y};
            #pragma unroll
            for (int p = 0; p < 4; p++) {
                acc[p][0] = fma2(ap[p], wd[0], acc[p][0]);
                acc[p][1] = fma2(ap[p], wd[1], acc[p][1]);
                acc[p][2] = fma2(ap[p], wd[2], acc[p][2]);
                acc[p][3] = fma2(ap[p], wd[3], acc[p][3]);
            }
        }
        __syncthreads();
    }

    // Transposed epilogue: for each of the 4 n's, 8 m's (two float4 stores)
    float4 bv = *(const float4*)&bias[bn + 4 * tx];
    float bb[4] = {bv.x, bv.y, bv.z, bv.w};
    #pragma unroll
    for (int nn = 0; nn < 4; nn++) {
        float2 f0 = unpack2(acc[0][nn]);
        float2 f1 = unpack2(acc[1][nn]);
        float2 f2 = unpack2(acc[2][nn]);
        float2 f3 = unpack2(acc[3][nn]);
        float4 o0 = make_float4(f0.x + bb[nn], f0.y + bb[nn], f1.x + bb[nn], f1.y + bb[nn]);
        float4 o1 = make_float4(f2.x + bb[nn], f2.y + bb[nn], f3.x + bb[nn], f3.y + bb[nn]);
        size_t base = (size_t)(bn + 4 * tx + nn) * M + bm + 8 * ty;
        *(float4*)&outT[base] = o0;
        *(float4*)&outT[base + 4] = o1;
    }
}

// ---------------------------------------------------------------------------
// Kernel 2b: Sw/Ow from the TRANSPOSED layout; each lane owns one row.
// 128 warps total: warps 0..63 -> subjT rows, 64..127 -> objT rows.
// ---------------------------------------------------------------------------
__global__ void __launch_bounds__(256)
swow_kernel(const float* __restrict__ subjT,
            const float* __restrict__ objT,
            const float* __restrict__ W_t,
            float* __restrict__ swow) {
    int gw = (blockIdx.x * 256 + threadIdx.x) >> 5;   // 0..127
    int lane = threadIdx.x & 31;
    const float* src = (gw < 64) ? subjT : objT;
    int row = ((gw & 63) << 5) + lane;                // 0..2047

    float4 a = make_float4(0.f, 0.f, 0.f, 0.f);
    const float4* wt4 = (const float4*)W_t;
    #pragma unroll 4
    for (int c = 0; c < C; c++) {
        float s = src[(size_t)c * M + row];
        float4 w = wt4[c];
        a.x += s * w.x; a.y += s * w.y; a.z += s * w.z; a.w += s * w.w;
    }
    int orow = (gw < 64) ? row : (M + row);
    ((float4*)swow)[orow] = a;
}

// ---------------------------------------------------------------------------
// Kernel 3a: rep = Sw[j]+Ow[i]+b - 2*sum_c min(s,o)*w, j-pair packed.
// 256 threads = 16 tx (j quads) x 16 ty; i = i0+ty, i0+ty+16.
// Tile 32i x 64j, CK=64; acc[2i][2jp][4h] = 16 u64 = 32 regs.
// ---------------------------------------------------------------------------
__global__ void __launch_bounds__(256)
rep_exp_kernel(const float* __restrict__ subjT,
               const float* __restrict__ objT,
               const float* __restrict__ W_t,
               const float* __restrict__ b_t,
               const float* __restrict__ swow,
               float* __restrict__ attn,
               float* __restrict__ part) {
    __shared__ float s_sh[CK * 64];     // [c][j]               16KB
    __shared__ float o_sh[CK * 64];     // [c][2i dup]          16KB
    __shared__ float w_sh[CK * 8];      // [c][2h dup] = -2*W_t  2KB

    const int tid = threadIdx.x;
    const int tx = tid & 15;           // j quad: j = 4tx..4tx+3
    const int ty = tid >> 4;           // 0..15; i = i0+ty, i0+ty+16
    const int jt = blockIdx.x;
    const int j0 = jt * TJ;
    const int i0 = blockIdx.y * TI;
    const int b  = blockIdx.z;

    u64 acc[2][2][4];
    #pragma unroll
    for (int p = 0; p < 2; p++)
        #pragma unroll
        for (int qq = 0; qq < 2; qq++)
            #pragma unroll
            for (int h = 0; h < 4; h++) acc[p][qq][h] = 0ULL;

    const int sbase_j = b * T + j0;
    const int sbase_i = b * T + i0;

    for (int ck = 0; ck < C / CK; ck++) {
        const int cbase = ck * CK;
        // s: [c][j] 64c x 64j floats
        #pragma unroll
        for (int l = 0; l < 4; l++) {
            int t = tid + l * 256;
            int c = t >> 4, jg = t & 15;
            float4 sv = *(const float4*)&subjT[(size_t)(cbase + c) * M + sbase_j + 4 * jg];
            *(float4*)&s_sh[c * 64 + 4 * jg] = sv;
        }
        // o: [c][2i dup]: 64c x 32i -> 64 dup floats per c
        #pragma unroll
        for (int l = 0; l < 4; l++) {
            int t = tid + l * 256;
            int c = t >> 4, ig = t & 15;
            float2 ov = *(const float2*)&objT[(size_t)(cbase + c) * M + sbase_i + 2 * ig];
            *(float4*)&o_sh[c * 64 + 4 * ig] = make_float4(ov.x, ov.x, ov.y, ov.y);
        }
        // w: [c][2h dup] = -2*W_t
        if (tid < 128) {
            int c = tid >> 1, hh = tid & 1;
            float2 wv = *(const float2*)&W_t[(cbase + c) * 4 + 2 * hh];
            *(float4*)&w_sh[c * 8 + 4 * hh] =
                make_float4(-2.f * wv.x, -2.f * wv.x, -2.f * wv.y, -2.f * wv.y);
        }
        __syncthreads();

        #pragma unroll 4
        for (int c = 0; c < CK; c++) {
            ulonglong2 S = *(const ulonglong2*)&s_sh[c * 64 + 4 * tx];
            u64 O0 = *(const u64*)&o_sh[c * 64 + 2 * ty];        // i = i0+ty
            u64 O1 = *(const u64*)&o_sh[c * 64 + 32 + 2 * ty];   // i = i0+ty+16
            ulonglong2 W0 = *(const ulonglong2*)&w_sh[c * 8];
            ulonglong2 W1 = *(const ulonglong2*)&w_sh[c * 8 + 4];
            u64 op[2] = {O0, O1};
            #pragma unroll
            for (int p = 0; p < 2; p++) {
                u64 m0 = fmin2(S.x, op[p]);
                acc[p][0][0] = fma2(m0, W0.x, acc[p][0][0]);
                acc[p][0][1] = fma2(m0, W0.y, acc[p][0][1]);
                acc[p][0][2] = fma2(m0, W1.x, acc[p][0][2]);
                acc[p][0][3] = fma2(m0, W1.y, acc[p][0][3]);
                u64 m1 = fmin2(S.y, op[p]);
                acc[p][1][0] = fma2(m1, W0.x, acc[p][1][0]);
                acc[p][1][1] = fma2(m1, W0.y, acc[p][1][1]);
                acc[p][1][2] = fma2(m1, W1.x, acc[p][1][2]);
                acc[p][1][3] = fma2(m1, W1.y, acc[p][1][3]);
            }
        }
        __syncthreads();
    }

    // Epilogue: z = relu(Sw[j] + Ow[i] + b + acc), e = exp(z)
    const float4 btv = *(const float4*)b_t;
    const float4* sw4 = (const float4*)swow;              // rows 0..M-1
    const float4* ow4 = (const float4*)swow + M;          // rows M..

    float4 swv[4];
    #pragma unroll
    for (int k = 0; k < 4; k++) swv[k] = sw4[b * T + j0 + 4 * tx + k];

    #pragma unroll
    for (int p = 0; p < 2; p++) {
        int i = i0 + ty + 16 * p;
        float4 owv = ow4[b * T + i];
        float base_x = owv.x + btv.x;
        float base_y = owv.y + btv.y;
        float base_z = owv.z + btv.z;
        float base_w = owv.w + btv.w;
        float4 ps = make_float4(0.f, 0.f, 0.f, 0.f);
        #pragma unroll
        for (int qq = 0; qq < 2; qq++) {
            float2 f0 = unpack2(acc[p][qq][0]);
            float2 f1 = unpack2(acc[p][qq][1]);
            float2 f2 = unpack2(acc[p][qq][2]);
            float2 f3 = unpack2(acc[p][qq][3]);
            #pragma unroll
            for (int k = 0; k < 2; k++) {
                int jj = 2 * qq + k;
                int j = j0 + 4 * tx + jj;
                float4 sv = swv[jj];
                float a0 = k ? f0.y : f0.x;
                float a1 = k ? f1.y : f1.x;
                float a2 = k ? f2.y : f2.x;
                float a3 = k ? f3.y : f3.x;
                float4 ev;
                ev.x = __expf(fmaxf(a0 + sv.x + base_x, 0.0f));
                ev.y = __expf(fmaxf(a1 + sv.y + base_y, 0.0f));
                ev.z = __expf(fmaxf(a2 + sv.z + base_z, 0.0f));
                ev.w = __expf(fmaxf(a3 + sv.w + base_w, 0.0f));
                *(float4*)&attn[(((size_t)(b * T + i)) * T + j) * HEADS] = ev;
                ps.x += ev.x; ps.y += ev.y; ps.z += ev.z; ps.w += ev.w;
            }
        }
        // reduce across the 16 tx lanes
        #pragma unroll
        for (int m = 8; m >= 1; m >>= 1) {
            ps.x += __shfl_xor_sync(0xffffffffu, ps.x, m);
            ps.y += __shfl_xor_sync(0xffffffffu, ps.y, m);
            ps.z += __shfl_xor_sync(0xffffffffu, ps.z, m);
            ps.w += __shfl_xor_sync(0xffffffffu, ps.w, m);
        }
        if (tx == 0)
            *(float4*)&part[((size_t)(b * T + i) * NJT + jt) * HEADS] = ps;
    }
}

// ---------------------------------------------------------------------------
// Kernel 3b: denominator + normalize + mask; 2 rows per block (shared mask j).
// ---------------------------------------------------------------------------
__global__ void __launch_bounds__(256)
normalize_kernel(const float* __restrict__ part,
                 const int* __restrict__ mask,
                 float* __restrict__ attn) {
    __shared__ float sinv[8];
    const int r = blockIdx.x;          // rows 2r, 2r+1
    const int tid = threadIdx.x;
    const int lane = tid & 31;
    const int wid = tid >> 5;

    if (wid < 2) {
        int row = 2 * r + wid;
        float v = part[row * (NJT * HEADS) + lane];
        v += __shfl_xor_sync(0xffffffffu, v, 4);
        v += __shfl_xor_sync(0xffffffffu, v, 8);
        v += __shfl_xor_sync(0xffffffffu, v, 16);
        if (lane < 4) sinv[wid * 4 + lane] = 1.0f / v;
    }
    __syncthreads();

    const float4 iv0 = make_float4(sinv[0], sinv[1], sinv[2], sinv[3]);
    const float4 iv1 = make_float4(sinv[4], sinv[5], sinv[6], sinv[7]);
    const int bi0 = 2 * r;
    const int b = bi0 >> 9;
    const int mi0 = mask[bi0];
    const int mi1 = mask[bi0 + 1];
    float4* arow0 = (float4*)attn + (size_t)bi0 * T;
    float4* arow1 = arow0 + T;

    #pragma unroll
    for (int rr = 0; rr < 2; rr++) {
        int j = tid + rr * 256;
        int mj = mask[b * T + j];
        float k0 = (mi0 && mj) ? 0.0f : 1.0f;
        float k1 = (mi1 && mj) ? 0.0f : 1.0f;
        float4 v0 = arow0[j];
        float4 v1 = arow1[j];
        v0.x *= iv0.x * k0; v0.y *= iv0.y * k0; v0.z *= iv0.z * k0; v0.w *= iv0.w * k0;
        v1.x *= iv1.x * k1; v1.y *= iv1.y * k1; v1.z *= iv1.z * k1; v1.w *= iv1.w * k1;
        arow0[j] = v0;
        arow1[j] = v1;
    }
}

// ---------------------------------------------------------------------------
extern "C" void kernel_launch(void* const* d_in, const int* in_sizes, int n_in,
                              void* d_out, int out_size) {
    const float* x      = (const float*)d_in[0];
    const float* W_subj = (const float*)d_in[1];
    const float* b_subj = (const float*)d_in[2];
    const float* W_obj  = (const float*)d_in[3];
    const float* b_obj  = (const float*)d_in[4];
    const float* W_t    = (const float*)d_in[5];
    const float* b_t    = (const float*)d_in[6];
    const int*   mask   = (const int*)d_in[7];

    float* out   = (float*)d_out;
    float* xnew  = out;                          // (B,T,2C)
    float* attn  = out + (size_t)M * C2;         // (B,T,T,HEADS)

    float *subjT, *objT, *part, *swow;
    cudaGetSymbolAddress((void**)&subjT, g_subjT);
    cudaGetSymbolAddress((void**)&objT, g_objT);
    cudaGetSymbolAddress((void**)&part, g_part);
    cudaGetSymbolAddress((void**)&swow, g_swow);

    pool_concat_kernel<<<(M * C2 + 255) / 256, 256>>>(x, xnew);

    dim3 gg(C / 64, M / 64, 2);   // (4, 32, 2) = 256 blocks
    gemm_kernel<<<gg, 128>>>(xnew, W_subj, b_subj, W_obj, b_obj, subjT, objT);

    swow_kernel<<<16, 256>>>(subjT, objT, W_t, swow);

    dim3 ga(T / TJ, T / TI, B);   // (8, 16, 4) = 512 blocks
    rep_exp_kernel<<<ga, 256>>>(subjT, objT, W_t, b_t, swow, attn, part);

    normalize_kernel<<<M / 2, 256>>>(part, mask, attn);
}

// round 14
// speedup vs baseline: 1.3150x; 1.3150x over previous
#include <cuda_runtime.h>
#include <cuda_bf16.h>
#include <math.h>

// Problem constants
#define B 4
#define T 512
#define C 256
#define C2 512
#define HEADS 4
#define MAXOFF 2
#define M (B * T)      // 2048

#define TI 32          // i-tile per block (rep)
#define TJ 64          // j-tile per block (rep)
#define NJT (T / TJ)   // 8 j-tiles
#define CK 128         // c chunk (rep)

typedef unsigned long long u64;

// Scratch (allocation-free: device globals)
__device__ float g_subj[M * C];
__device__ float g_obj[M * C];
__device__ float g_part[M * NJT * HEADS];       // partial exp-sums per j-tile
__device__ float g_swpart[2 * 4 * M * HEADS];   // [z][bnTile][m][h] partial Sw/Ow

// packed f32x2 helpers
static __device__ __forceinline__ u64 fma2(u64 a, u64 b, u64 c) {
    u64 r; asm("fma.rn.f32x2 %0, %1, %2, %3;" : "=l"(r) : "l"(a), "l"(b), "l"(c)); return r;
}
static __device__ __forceinline__ float2 unpack2(u64 v) {
    float2 r; asm("mov.b64 {%0, %1}, %2;" : "=f"(r.x), "=f"(r.y) : "l"(v)); return r;
}
static __device__ __forceinline__ u64 pack2(float lo, float hi) {
    u64 r; asm("mov.b64 %0, {%1, %2};" : "=l"(r) : "f"(lo), "f"(hi)); return r;
}
// packed min (FMNMX on ALU pipe); union form lets ptxas pair-allocate
static __device__ __forceinline__ u64 fmin2(u64 a, u64 b) {
    union { u64 v; float2 f; } ua, ub, uc;
    ua.v = a; ub.v = b;
    uc.f.x = fminf(ua.f.x, ub.f.x);
    uc.f.y = fminf(ua.f.y, ub.f.y);
    return uc.v;
}

// ---------------------------------------------------------------------------
// Kernel 1: max-pool along channel (window 5, pad 2) + concat -> x_new
// ---------------------------------------------------------------------------
__global__ void pool_concat_kernel(const float* __restrict__ x,
                                   float* __restrict__ xnew) {
    int idx = blockIdx.x * 256 + threadIdx.x;
    if (idx >= M * C2) return;
    int cc = idx & (C2 - 1);
    int bt = idx >> 9;
    const float* xr = x + bt * C;
    float v;
    if (cc < C) {
        int lo = cc - MAXOFF; if (lo < 0) lo = 0;
        int hi = cc + MAXOFF; if (hi > C - 1) hi = C - 1;
        v = -INFINITY;
        #pragma unroll 5
        for (int c = lo; c <= hi; c++) v = fmaxf(v, xr[c]);
    } else {
        v = xr[cc - C];
    }
    xnew[idx] = v;
}

// ---------------------------------------------------------------------------
// Kernel 2: projection GEMMs, m-packed f32x2 (R11 core) + fused Sw/Ow
// partials.  Tile 64m x 64n, 128 threads (tx = n-quad, ty = m-octet).
// Each block writes swpart[z][bn/64][m][0..3] for its 64 m rows
// (partial over its 64 n's) — unique writer, deterministic.
// ---------------------------------------------------------------------------
__global__ void __launch_bounds__(128)
gemm_kernel(const float* __restrict__ A,
            const float* __restrict__ W0,
            const float* __restrict__ b0,
            const float* __restrict__ W1,
            const float* __restrict__ b1,
            const float* __restrict__ W_t,
            float* __restrict__ out0,
            float* __restrict__ out1,
            float* __restrict__ swpart) {
    __shared__ float As[16 * 68];   // [k][m], stride 68
    __shared__ float Ws[16 * 68];   // [k][n], stride 68

    const float* W    = blockIdx.z ? W1 : W0;
    const float* bias = blockIdx.z ? b1 : b0;
    float* out        = blockIdx.z ? out1 : out0;

    const int tid = threadIdx.x;
    const int tx = tid & 15;           // n quad: n = 4tx..4tx+3
    const int ty = tid >> 4;           // m octet: m = 8ty..8ty+7  (0..7)
    const int bm = blockIdx.y * 64;
    const int bn = blockIdx.x * 64;

    u64 acc[4][4];
    #pragma unroll
    for (int p = 0; p < 4; p++)
        #pragma unroll
        for (int n = 0; n < 4; n++) acc[p][n] = 0ULL;

    for (int k0 = 0; k0 < C2; k0 += 16) {
        #pragma unroll
        for (int l = 0; l < 2; l++) {
            int idx = tid + l * 128;
            int m = idx >> 2, kq = idx & 3;
            float4 av = *(const float4*)&A[(bm + m) * C2 + k0 + 4 * kq];
            As[(4 * kq + 0) * 68 + m] = av.x;
            As[(4 * kq + 1) * 68 + m] = av.y;
            As[(4 * kq + 2) * 68 + m] = av.z;
            As[(4 * kq + 3) * 68 + m] = av.w;
        }
        #pragma unroll
        for (int l = 0; l < 2; l++) {
            int idx = tid + l * 128;
            int nq = idx & 15, kw = idx >> 4;
            float4 wv = *(const float4*)&W[(k0 + kw) * C + bn + 4 * nq];
            *(float4*)&Ws[kw * 68 + 4 * nq] = wv;
        }
        __syncthreads();

        #pragma unroll
        for (int k = 0; k < 16; k++) {
            ulonglong2 A01 = *(const ulonglong2*)&As[k * 68 + 8 * ty];
            ulonglong2 A23 = *(const ulonglong2*)&As[k * 68 + 8 * ty + 4];
            float4 wv = *(const float4*)&Ws[k * 68 + 4 * tx];
            u64 wd[4];
            wd[0] = pack2(wv.x, wv.x);
            wd[1] = pack2(wv.y, wv.y);
            wd[2] = pack2(wv.z, wv.z);
            wd[3] = pack2(wv.w, wv.w);
            u64 ap[4] = {A01.x, A01.y, A23.x, A23.y};
            #pragma unroll
            for (int p = 0; p < 4; p++) {
                acc[p][0] = fma2(ap[p], wd[0], acc[p][0]);
                acc[p][1] = fma2(ap[p], wd[1], acc[p][1]);
                acc[p][2] = fma2(ap[p], wd[2], acc[p][2]);
                acc[p][3] = fma2(ap[p], wd[3], acc[p][3]);
            }
        }
        __syncthreads();
    }

    // W_t rows for this thread's 4 n's
    float wmat[4][4];
    #pragma unroll
    for (int nn = 0; nn < 4; nn++) {
        float4 w = *(const float4*)&W_t[(bn + 4 * tx + nn) * 4];
        wmat[nn][0] = w.x; wmat[nn][1] = w.y; wmat[nn][2] = w.z; wmat[nn][3] = w.w;
    }

    float4 bv = *(const float4*)&bias[bn + 4 * tx];
    float red[4][2][4];
    #pragma unroll
    for (int p = 0; p < 4; p++) {
        float2 f0 = unpack2(acc[p][0]);
        float2 f1 = unpack2(acc[p][1]);
        float2 f2 = unpack2(acc[p][2]);
        float2 f3 = unpack2(acc[p][3]);
        float4 rlo = make_float4(f0.x + bv.x, f1.x + bv.y, f2.x + bv.z, f3.x + bv.w);
        float4 rhi = make_float4(f0.y + bv.x, f1.y + bv.y, f2.y + bv.z, f3.y + bv.w);
        int m = bm + 8 * ty + 2 * p;
        *(float4*)&out[(size_t)m * C + bn + 4 * tx] = rlo;
        *(float4*)&out[(size_t)(m + 1) * C + bn + 4 * tx] = rhi;
        #pragma unroll
        for (int h = 0; h < 4; h++) {
            red[p][0][h] = rlo.x * wmat[0][h] + rlo.y * wmat[1][h]
                         + rlo.z * wmat[2][h] + rlo.w * wmat[3][h];
            red[p][1][h] = rhi.x * wmat[0][h] + rhi.y * wmat[1][h]
                         + rhi.z * wmat[2][h] + rhi.w * wmat[3][h];
        }
    }
    // reduce over the 16 tx lanes (lanes 0-15 / 16-31 are separate ty groups)
    #pragma unroll
    for (int p = 0; p < 4; p++)
        #pragma unroll
        for (int r = 0; r < 2; r++)
            #pragma unroll
            for (int h = 0; h < 4; h++) {
                float v = red[p][r][h];
                v += __shfl_xor_sync(0xffffffffu, v, 1);
                v += __shfl_xor_sync(0xffffffffu, v, 2);
                v += __shfl_xor_sync(0xffffffffu, v, 4);
                v += __shfl_xor_sync(0xffffffffu, v, 8);
                red[p][r][h] = v;
            }
    if (tx == 0) {
        float4* sp4 = (float4*)swpart;
        size_t slab = (size_t)(blockIdx.z * 4 + blockIdx.x) * M;
        #pragma unroll
        for (int p = 0; p < 4; p++) {
            int m = bm + 8 * ty + 2 * p;
            sp4[slab + m]     = make_float4(red[p][0][0], red[p][0][1], red[p][0][2], red[p][0][3]);
            sp4[slab + m + 1] = make_float4(red[p][1][0], red[p][1][1], red[p][1][2], red[p][1][3]);
        }
    }
}

// ---------------------------------------------------------------------------
// Kernel 3a (R7/R11 shape): rep = Sw[j]+Ow[i]+b - 2*sum_c min(s,o)*w.
// 128 threads = 16 tx (j, stride-16) x 8 ty (i, stride-8); 4i x 4j x 4h.
// Sw/Ow read as the sum of 4 gemm partial slabs.
// ---------------------------------------------------------------------------
__global__ void __launch_bounds__(128)
rep_exp_kernel(const float* __restrict__ subj,
               const float* __restrict__ obj,
               const float* __restrict__ W_t,
               const float* __restrict__ b_t,
               const float* __restrict__ swpart,
               float* __restrict__ attn,
               float* __restrict__ part) {
    __shared__ float s_sh[TJ * CK];     // [jrow][c], swizzled (32KB)
    __shared__ float o_sh[TI * CK];     // [irow][c], swizzled (16KB)
    __shared__ float w_sh[HEADS * C];   // [h][c] = -2*W_t (4KB)

    const int tid = threadIdx.x;
    const int tx = tid & 15;           // j: j0 + tx + 16q
    const int ty = tid >> 4;           // i: i0 + ty + 8p   (0..7)
    const int jt = blockIdx.x;
    const int j0 = jt * TJ;
    const int i0 = blockIdx.y * TI;
    const int b  = blockIdx.z;

    #pragma unroll
    for (int c = tid; c < C; c += 128) {
        float4 wv = *(const float4*)&W_t[c * 4];
        w_sh[0 * C + c] = -2.0f * wv.x;
        w_sh[1 * C + c] = -2.0f * wv.y;
        w_sh[2 * C + c] = -2.0f * wv.z;
        w_sh[3 * C + c] = -2.0f * wv.w;
    }

    u64 acc[4][4][4];
    #pragma unroll
    for (int p = 0; p < 4; p++)
        #pragma unroll
        for (int q = 0; q < 4; q++)
            #pragma unroll
            for (int h = 0; h < 4; h++) acc[p][q][h] = 0ULL;

    const int swj = tx & 7;
    const float* sp[4];
    const float* op[4];
    #pragma unroll
    for (int q = 0; q < 4; q++) sp[q] = s_sh + (tx + 16 * q) * CK;
    #pragma unroll
    for (int p = 0; p < 4; p++) op[p] = o_sh + (ty + 8 * p) * CK;

    for (int ck = 0; ck < C / CK; ck++) {
        const int cbase = ck * CK;
        #pragma unroll
        for (int l = 0; l < 16; l++) {
            int t = tid + l * 128;
            int row = t >> 5;          // 0..63
            int ccg = t & 31;
            int phys = (ccg ^ (row & 7)) << 2;
            float4 sv = *(const float4*)&subj[(b * T + j0 + row) * C + cbase + ccg * 4];
            *(float4*)&s_sh[row * CK + phys] = sv;
        }
        #pragma unroll
        for (int l = 0; l < 8; l++) {
            int t = tid + l * 128;
            int row = t >> 5;          // 0..31
            int ccg = t & 31;
            int phys = (ccg ^ (row & 7)) << 2;
            float4 ov = *(const float4*)&obj[(b * T + i0 + row) * C + cbase + ccg * 4];
            *(float4*)&o_sh[row * CK + phys] = ov;
        }
        __syncthreads();

        const float* wp0 = w_sh + 0 * C + cbase;
        const float* wp1 = w_sh + 1 * C + cbase;
        const float* wp2 = w_sh + 2 * C + cbase;
        const float* wp3 = w_sh + 3 * C + cbase;

        #pragma unroll 1
        for (int g = 0; g < CK / 4; g++) {
            const int gs = ((g ^ swj) << 2);
            const int gi = ((g ^ ty) << 2);
            ulonglong2 S[4], P[4], Wv[4];
            #pragma unroll
            for (int q = 0; q < 4; q++) S[q] = *(const ulonglong2*)(sp[q] + gs);
            #pragma unroll
            for (int p = 0; p < 4; p++) P[p] = *(const ulonglong2*)(op[p] + gi);
            Wv[0] = *(const ulonglong2*)(wp0 + g * 4);
            Wv[1] = *(const ulonglong2*)(wp1 + g * 4);
            Wv[2] = *(const ulonglong2*)(wp2 + g * 4);
            Wv[3] = *(const ulonglong2*)(wp3 + g * 4);

            #pragma unroll
            for (int p = 0; p < 4; p++) {
                #pragma unroll
                for (int q = 0; q < 4; q++) {
                    u64 m0 = fmin2(S[q].x, P[p].x);
                    acc[p][q][0] = fma2(m0, Wv[0].x, acc[p][q][0]);
                    acc[p][q][1] = fma2(m0, Wv[1].x, acc[p][q][1]);
                    acc[p][q][2] = fma2(m0, Wv[2].x, acc[p][q][2]);
                    acc[p][q][3] = fma2(m0, Wv[3].x, acc[p][q][3]);
                    u64 m1 = fmin2(S[q].y, P[p].y);
                    acc[p][q][0] = fma2(m1, Wv[0].y, acc[p][q][0]);
                    acc[p][q][1] = fma2(m1, Wv[1].y, acc[p][q][1]);
                    acc[p][q][2] = fma2(m1, Wv[2].y, acc[p][q][2]);
                    acc[p][q][3] = fma2(m1, Wv[3].y, acc[p][q][3]);
                }
            }
        }
        __syncthreads();
    }

    const float4 btv = *(const float4*)b_t;
    const float4* sp4 = (const float4*)swpart;   // [z*4+t][m] float4 slabs

    // Ow[i] = sum of slabs 4..7; Sw[j] = sum of slabs 0..3
    float4 owv[4];
    #pragma unroll
    for (int p = 0; p < 4; p++) {
        int row = b * T + i0 + ty + 8 * p;
        float4 a0 = sp4[(size_t)4 * M + row];
        float4 a1 = sp4[(size_t)5 * M + row];
        float4 a2 = sp4[(size_t)6 * M + row];
        float4 a3 = sp4[(size_t)7 * M + row];
        owv[p] = make_float4(a0.x + a1.x + a2.x + a3.x,
                             a0.y + a1.y + a2.y + a3.y,
                             a0.z + a1.z + a2.z + a3.z,
                             a0.w + a1.w + a2.w + a3.w);
    }

    #pragma unroll
    for (int p = 0; p < 4; p++) {
        int i = i0 + ty + 8 * p;
        float4 ps = make_float4(0.f, 0.f, 0.f, 0.f);
        float base_x = owv[p].x + btv.x;
        float base_y = owv[p].y + btv.y;
        float base_z = owv[p].z + btv.z;
        float base_w = owv[p].w + btv.w;
        #pragma unroll
        for (int q = 0; q < 4; q++) {
            int j = j0 + tx + 16 * q;
            int row = b * T + j;
            float4 s0 = sp4[row];
            float4 s1 = sp4[(size_t)M + row];
            float4 s2 = sp4[(size_t)2 * M + row];
            float4 s3 = sp4[(size_t)3 * M + row];
            float4 swv = make_float4(s0.x + s1.x + s2.x + s3.x,
                                     s0.y + s1.y + s2.y + s3.y,
                                     s0.z + s1.z + s2.z + s3.z,
                                     s0.w + s1.w + s2.w + s3.w);
            float2 f0 = unpack2(acc[p][q][0]);
            float2 f1 = unpack2(acc[p][q][1]);
            float2 f2 = unpack2(acc[p][q][2]);
            float2 f3 = unpack2(acc[p][q][3]);
            float4 ev;
            ev.x = __expf(fmaxf(f0.x + f0.y + swv.x + base_x, 0.0f));
            ev.y = __expf(fmaxf(f1.x + f1.y + swv.y + base_y, 0.0f));
            ev.z = __expf(fmaxf(f2.x + f2.y + swv.z + base_z, 0.0f));
            ev.w = __expf(fmaxf(f3.x + f3.y + swv.w + base_w, 0.0f));
            *(float4*)&attn[(((size_t)(b * T + i)) * T + j) * HEADS] = ev;
            ps.x += ev.x; ps.y += ev.y; ps.z += ev.z; ps.w += ev.w;
        }
        #pragma unroll
        for (int m = 8; m >= 1; m >>= 1) {
            ps.x += __shfl_xor_sync(0xffffffffu, ps.x, m);
            ps.y += __shfl_xor_sync(0xffffffffu, ps.y, m);
            ps.z += __shfl_xor_sync(0xffffffffu, ps.z, m);
            ps.w += __shfl_xor_sync(0xffffffffu, ps.w, m);
        }
        if (tx == 0)
            *(float4*)&part[((size_t)(b * T + i) * NJT + jt) * HEADS] = ps;
    }
}

// ---------------------------------------------------------------------------
// Kernel 3b: denominator + normalize + mask; 2 rows per block (shared mask j).
// ---------------------------------------------------------------------------
__global__ void __launch_bounds__(256)
normalize_kernel(const float* __restrict__ part,
                 const int* __restrict__ mask,
                 float* __restrict__ attn) {
    __shared__ float sinv[8];
    const int r = blockIdx.x;          // rows 2r, 2r+1
    const int tid = threadIdx.x;
    const int lane = tid & 31;
    const int wid = tid >> 5;

    if (wid < 2) {
        int row = 2 * r + wid;
        float v = part[row * (NJT * HEADS) + lane];
        v += __shfl_xor_sync(0xffffffffu, v, 4);
        v += __shfl_xor_sync(0xffffffffu, v, 8);
        v += __shfl_xor_sync(0xffffffffu, v, 16);
        if (lane < 4) sinv[wid * 4 + lane] = 1.0f / v;
    }
    __syncthreads();

    const float4 iv0 = make_float4(sinv[0], sinv[1], sinv[2], sinv[3]);
    const float4 iv1 = make_float4(sinv[4], sinv[5], sinv[6], sinv[7]);
    const int bi0 = 2 * r;
    const int b = bi0 >> 9;
    const int mi0 = mask[bi0];
    const int mi1 = mask[bi0 + 1];
    float4* arow0 = (float4*)attn + (size_t)bi0 * T;
    float4* arow1 = arow0 + T;

    #pragma unroll
    for (int rr = 0; rr < 2; rr++) {
        int j = tid + rr * 256;
        int mj = mask[b * T + j];
        float k0 = (mi0 && mj) ? 0.0f : 1.0f;
        float k1 = (mi1 && mj) ? 0.0f : 1.0f;
        float4 v0 = arow0[j];
        float4 v1 = arow1[j];
        v0.x *= iv0.x * k0; v0.y *= iv0.y * k0; v0.z *= iv0.z * k0; v0.w *= iv0.w * k0;
        v1.x *= iv1.x * k1; v1.y *= iv1.y * k1; v1.z *= iv1.z * k1; v1.w *= iv1.w * k1;
        arow0[j] = v0;
        arow1[j] = v1;
    }
}

// ---------------------------------------------------------------------------
extern "C" void kernel_launch(void* const* d_in, const int* in_sizes, int n_in,
                              void* d_out, int out_size) {
    const float* x      = (const float*)d_in[0];
    const float* W_subj = (const float*)d_in[1];
    const float* b_subj = (const float*)d_in[2];
    const float* W_obj  = (const float*)d_in[3];
    const float* b_obj  = (const float*)d_in[4];
    const float* W_t    = (const float*)d_in[5];
    const float* b_t    = (const float*)d_in[6];
    const int*   mask   = (const int*)d_in[7];

    float* out   = (float*)d_out;
    float* xnew  = out;                          // (B,T,2C)
    float* attn  = out + (size_t)M * C2;         // (B,T,T,HEADS)

    float *subj, *obj, *part, *swpart;
    cudaGetSymbolAddress((void**)&subj, g_subj);
    cudaGetSymbolAddress((void**)&obj, g_obj);
    cudaGetSymbolAddress((void**)&part, g_part);
    cudaGetSymbolAddress((void**)&swpart, g_swpart);

    pool_concat_kernel<<<(M * C2 + 255) / 256, 256>>>(x, xnew);

    dim3 gg(C / 64, M / 64, 2);   // (4, 32, 2) = 256 blocks
    gemm_kernel<<<gg, 128>>>(xnew, W_subj, b_subj, W_obj, b_obj, W_t,
                             subj, obj, swpart);

    dim3 ga(T / TJ, T / TI, B);   // (8, 16, 4) = 512 blocks
    rep_exp_kernel<<<ga, 128>>>(subj, obj, W_t, b_t, swpart, attn, part);

    normalize_kernel<<<M / 2, 256>>>(part, mask, attn);
}

// round 15
// speedup vs baseline: 1.4272x; 1.0853x over previous
#include <cuda_runtime.h>
#include <cuda_bf16.h>
#include <math.h>

// Problem constants
#define B 4
#define T 512
#define C 256
#define C2 512
#define HEADS 4
#define MAXOFF 2
#define M (B * T)      // 2048

#define TI 32          // i-tile per block (rep)
#define TJ 64          // j-tile per block (rep)
#define NJT (T / TJ)   // 8 j-tiles
#define CK 128         // c chunk (rep)

typedef unsigned long long u64;

// Scratch (allocation-free: device globals)
__device__ float g_subj[M * C];
__device__ float g_obj[M * C];
__device__ float g_part[M * NJT * HEADS];       // partial exp-sums per j-tile
__device__ float g_swow[2 * M * HEADS];         // Sw rows 0..M-1, Ow rows M..

// packed f32x2 helpers
static __device__ __forceinline__ u64 fma2(u64 a, u64 b, u64 c) {
    u64 r; asm("fma.rn.f32x2 %0, %1, %2, %3;" : "=l"(r) : "l"(a), "l"(b), "l"(c)); return r;
}
static __device__ __forceinline__ float2 unpack2(u64 v) {
    float2 r; asm("mov.b64 {%0, %1}, %2;" : "=f"(r.x), "=f"(r.y) : "l"(v)); return r;
}
static __device__ __forceinline__ u64 pack2(float lo, float hi) {
    u64 r; asm("mov.b64 %0, {%1, %2};" : "=l"(r) : "f"(lo), "f"(hi)); return r;
}
// packed min (FMNMX on ALU pipe); union form lets ptxas pair-allocate
static __device__ __forceinline__ u64 fmin2(u64 a, u64 b) {
    union { u64 v; float2 f; } ua, ub, uc;
    ua.v = a; ub.v = b;
    uc.f.x = fminf(ua.f.x, ub.f.x);
    uc.f.y = fminf(ua.f.y, ub.f.y);
    return uc.v;
}

// ---------------------------------------------------------------------------
// Kernel 2: projection GEMMs, m-packed f32x2 (R11 core) with the max-pool
// + concat FUSED into the A-loader.  A[m][k] = pooled x (k<256) or x[k-256].
// Block (x==0, z==0) also writes xnew (unique writer, deterministic).
// Tile 64m x 64n, 128 threads (tx 0..15 = n-quad, ty 0..7 = m-octet).
// ---------------------------------------------------------------------------
__global__ void __launch_bounds__(128)
gemm_kernel(const float* __restrict__ x,
            const float* __restrict__ W0,
            const float* __restrict__ b0,
            const float* __restrict__ W1,
            const float* __restrict__ b1,
            float* __restrict__ out0,
            float* __restrict__ out1,
            float* __restrict__ xnew) {
    __shared__ float As[16 * 68];   // [k][m], stride 68
    __shared__ float Ws[16 * 68];   // [k][n], stride 68

    const float* W    = blockIdx.z ? W1 : W0;
    const float* bias = blockIdx.z ? b1 : b0;
    float* out        = blockIdx.z ? out1 : out0;

    const int tid = threadIdx.x;
    const int tx = tid & 15;           // n quad: n = 4tx..4tx+3
    const int ty = tid >> 4;           // m octet: m = 8ty..8ty+7  (0..7)
    const int bm = blockIdx.y * 64;
    const int bn = blockIdx.x * 64;
    const bool writer = (blockIdx.x == 0) && (blockIdx.z == 0);

    u64 acc[4][4];
    #pragma unroll
    for (int p = 0; p < 4; p++)
        #pragma unroll
        for (int n = 0; n < 4; n++) acc[p][n] = 0ULL;

    for (int k0 = 0; k0 < C2; k0 += 16) {
        // A chunk 64m x 16k, computed from x on the fly
        #pragma unroll
        for (int l = 0; l < 2; l++) {
            int idx = tid + l * 128;
            int m = idx >> 2, kq = idx & 3;
            int kk = k0 + 4 * kq;
            const float* xr = x + (size_t)(bm + m) * C;
            float4 av;
            if (kk >= C) {
                av = *(const float4*)&xr[kk - C];
            } else {
                float4 fb = *(const float4*)&xr[kk];
                float faz = -INFINITY, faw = -INFINITY;
                float fcx = -INFINITY, fcy = -INFINITY;
                if (kk >= 4) {
                    float4 fa = *(const float4*)&xr[kk - 4];
                    faz = fa.z; faw = fa.w;
                }
                if (kk <= C - 8) {
                    float4 fc = *(const float4*)&xr[kk + 4];
                    fcx = fc.x; fcy = fc.y;
                }
                av.x = fmaxf(fmaxf(faz, faw), fmaxf(fb.x, fmaxf(fb.y, fb.z)));
                av.y = fmaxf(faw, fmaxf(fmaxf(fb.x, fb.y), fmaxf(fb.z, fb.w)));
                av.z = fmaxf(fmaxf(fb.x, fb.y), fmaxf(fmaxf(fb.z, fb.w), fcx));
                av.w = fmaxf(fmaxf(fb.y, fb.z), fmaxf(fmaxf(fb.w, fcx), fcy));
            }
            if (writer)
                *(float4*)&xnew[(size_t)(bm + m) * C2 + kk] = av;
            As[(4 * kq + 0) * 68 + m] = av.x;
            As[(4 * kq + 1) * 68 + m] = av.y;
            As[(4 * kq + 2) * 68 + m] = av.z;
            As[(4 * kq + 3) * 68 + m] = av.w;
        }
        #pragma unroll
        for (int l = 0; l < 2; l++) {
            int idx = tid + l * 128;
            int nq = idx & 15, kw = idx >> 4;
            float4 wv = *(const float4*)&W[(k0 + kw) * C + bn + 4 * nq];
            *(float4*)&Ws[kw * 68 + 4 * nq] = wv;
        }
        __syncthreads();

        #pragma unroll
        for (int k = 0; k < 16; k++) {
            ulonglong2 A01 = *(const ulonglong2*)&As[k * 68 + 8 * ty];
            ulonglong2 A23 = *(const ulonglong2*)&As[k * 68 + 8 * ty + 4];
            float4 wv = *(const float4*)&Ws[k * 68 + 4 * tx];
            u64 wd[4];
            wd[0] = pack2(wv.x, wv.x);
            wd[1] = pack2(wv.y, wv.y);
            wd[2] = pack2(wv.z, wv.z);
            wd[3] = pack2(wv.w, wv.w);
            u64 ap[4] = {A01.x, A01.y, A23.x, A23.y};
            #pragma unroll
            for (int p = 0; p < 4; p++) {
                acc[p][0] = fma2(ap[p], wd[0], acc[p][0]);
                acc[p][1] = fma2(ap[p], wd[1], acc[p][1]);
                acc[p][2] = fma2(ap[p], wd[2], acc[p][2]);
                acc[p][3] = fma2(ap[p], wd[3], acc[p][3]);
            }
        }
        __syncthreads();
    }

    float4 bv = *(const float4*)&bias[bn + 4 * tx];
    #pragma unroll
    for (int p = 0; p < 4; p++) {
        float2 f0 = unpack2(acc[p][0]);
        float2 f1 = unpack2(acc[p][1]);
        float2 f2 = unpack2(acc[p][2]);
        float2 f3 = unpack2(acc[p][3]);
        float4 rlo = make_float4(f0.x + bv.x, f1.x + bv.y, f2.x + bv.z, f3.x + bv.w);
        float4 rhi = make_float4(f0.y + bv.x, f1.y + bv.y, f2.y + bv.z, f3.y + bv.w);
        int m = bm + 8 * ty + 2 * p;
        *(float4*)&out[(size_t)m * C + bn + 4 * tx] = rlo;
        *(float4*)&out[(size_t)(m + 1) * C + bn + 4 * tx] = rhi;
    }
}

// ---------------------------------------------------------------------------
// Kernel 2b: Sw[j,h] = subj[j,:] @ W_t  and  Ow[i,h] = obj[i,:] @ W_t.
// ---------------------------------------------------------------------------
__global__ void __launch_bounds__(128)
swow_kernel(const float* __restrict__ subj,
            const float* __restrict__ obj,
            const float* __restrict__ W_t,
            float* __restrict__ swow) {
    int gw = (blockIdx.x * 128 + threadIdx.x) >> 5;   // 0..4095
    int lane = threadIdx.x & 31;
    const float* src = (gw < M) ? subj : obj;
    int row = gw & (M - 1);

    float4 a = make_float4(0.f, 0.f, 0.f, 0.f);
    const float4* wt4 = (const float4*)W_t;
    #pragma unroll
    for (int c = lane; c < C; c += 32) {
        float s = src[row * C + c];
        float4 w = wt4[c];
        a.x += s * w.x; a.y += s * w.y; a.z += s * w.z; a.w += s * w.w;
    }
    #pragma unroll
    for (int m = 16; m >= 1; m >>= 1) {
        a.x += __shfl_xor_sync(0xffffffffu, a.x, m);
        a.y += __shfl_xor_sync(0xffffffffu, a.y, m);
        a.z += __shfl_xor_sync(0xffffffffu, a.z, m);
        a.w += __shfl_xor_sync(0xffffffffu, a.w, m);
    }
    if (lane == 0) ((float4*)swow)[gw] = a;
}

// ---------------------------------------------------------------------------
// Kernel 3a (R7/R11 shape): rep = Sw[j]+Ow[i]+b - 2*sum_c min(s,o)*w.
// 128 threads = 16 tx (j, stride-16) x 8 ty (i, stride-8); 4i x 4j x 4h.
// ---------------------------------------------------------------------------
__global__ void __launch_bounds__(128)
rep_exp_kernel(const float* __restrict__ subj,
               const float* __restrict__ obj,
               const float* __restrict__ W_t,
               const float* __restrict__ b_t,
               const float* __restrict__ swow,
               float* __restrict__ attn,
               float* __restrict__ part) {
    __shared__ float s_sh[TJ * CK];     // [jrow][c], swizzled (32KB)
    __shared__ float o_sh[TI * CK];     // [irow][c], swizzled (16KB)
    __shared__ float w_sh[HEADS * C];   // [h][c] = -2*W_t (4KB)

    const int tid = threadIdx.x;
    const int tx = tid & 15;           // j: j0 + tx + 16q
    const int ty = tid >> 4;           // i: i0 + ty + 8p   (0..7)
    const int jt = blockIdx.x;
    const int j0 = jt * TJ;
    const int i0 = blockIdx.y * TI;
    const int b  = blockIdx.z;

    #pragma unroll
    for (int c = tid; c < C; c += 128) {
        float4 wv = *(const float4*)&W_t[c * 4];
        w_sh[0 * C + c] = -2.0f * wv.x;
        w_sh[1 * C + c] = -2.0f * wv.y;
        w_sh[2 * C + c] = -2.0f * wv.z;
        w_sh[3 * C + c] = -2.0f * wv.w;
    }

    u64 acc[4][4][4];
    #pragma unroll
    for (int p = 0; p < 4; p++)
        #pragma unroll
        for (int q = 0; q < 4; q++)
            #pragma unroll
            for (int h = 0; h < 4; h++) acc[p][q][h] = 0ULL;

    const int swj = tx & 7;
    const float* sp[4];
    const float* op[4];
    #pragma unroll
    for (int q = 0; q < 4; q++) sp[q] = s_sh + (tx + 16 * q) * CK;
    #pragma unroll
    for (int p = 0; p < 4; p++) op[p] = o_sh + (ty + 8 * p) * CK;

    for (int ck = 0; ck < C / CK; ck++) {
        const int cbase = ck * CK;
        #pragma unroll
        for (int l = 0; l < 16; l++) {
            int t = tid + l * 128;
            int row = t >> 5;          // 0..63
            int ccg = t & 31;
            int phys = (ccg ^ (row & 7)) << 2;
            float4 sv = *(const float4*)&subj[(b * T + j0 + row) * C + cbase + ccg * 4];
            *(float4*)&s_sh[row * CK + phys] = sv;
        }
        #pragma unroll
        for (int l = 0; l < 8; l++) {
            int t = tid + l * 128;
            int row = t >> 5;          // 0..31
            int ccg = t & 31;
            int phys = (ccg ^ (row & 7)) << 2;
            float4 ov = *(const float4*)&obj[(b * T + i0 + row) * C + cbase + ccg * 4];
            *(float4*)&o_sh[row * CK + phys] = ov;
        }
        __syncthreads();

        const float* wp0 = w_sh + 0 * C + cbase;
        const float* wp1 = w_sh + 1 * C + cbase;
        const float* wp2 = w_sh + 2 * C + cbase;
        const float* wp3 = w_sh + 3 * C + cbase;

        #pragma unroll 1
        for (int g = 0; g < CK / 4; g++) {
            const int gs = ((g ^ swj) << 2);
            const int gi = ((g ^ ty) << 2);
            ulonglong2 S[4], P[4], Wv[4];
            #pragma unroll
            for (int q = 0; q < 4; q++) S[q] = *(const ulonglong2*)(sp[q] + gs);
            #pragma unroll
            for (int p = 0; p < 4; p++) P[p] = *(const ulonglong2*)(op[p] + gi);
            Wv[0] = *(const ulonglong2*)(wp0 + g * 4);
            Wv[1] = *(const ulonglong2*)(wp1 + g * 4);
            Wv[2] = *(const ulonglong2*)(wp2 + g * 4);
            Wv[3] = *(const ulonglong2*)(wp3 + g * 4);

            #pragma unroll
            for (int p = 0; p < 4; p++) {
                #pragma unroll
                for (int q = 0; q < 4; q++) {
                    u64 m0 = fmin2(S[q].x, P[p].x);
                    acc[p][q][0] = fma2(m0, Wv[0].x, acc[p][q][0]);
                    acc[p][q][1] = fma2(m0, Wv[1].x, acc[p][q][1]);
                    acc[p][q][2] = fma2(m0, Wv[2].x, acc[p][q][2]);
                    acc[p][q][3] = fma2(m0, Wv[3].x, acc[p][q][3]);
                    u64 m1 = fmin2(S[q].y, P[p].y);
                    acc[p][q][0] = fma2(m1, Wv[0].y, acc[p][q][0]);
                    acc[p][q][1] = fma2(m1, Wv[1].y, acc[p][q][1]);
                    acc[p][q][2] = fma2(m1, Wv[2].y, acc[p][q][2]);
                    acc[p][q][3] = fma2(m1, Wv[3].y, acc[p][q][3]);
                }
            }
        }
        __syncthreads();
    }

    const float4 btv = *(const float4*)b_t;
    const float4* sw4 = (const float4*)swow;              // rows 0..M-1
    const float4* ow4 = (const float4*)swow + M;          // rows M..

    float4 owv[4];
    #pragma unroll
    for (int p = 0; p < 4; p++) owv[p] = ow4[b * T + i0 + ty + 8 * p];

    #pragma unroll
    for (int p = 0; p < 4; p++) {
        int i = i0 + ty + 8 * p;
        float4 ps = make_float4(0.f, 0.f, 0.f, 0.f);
        float base_x = owv[p].x + btv.x;
        float base_y = owv[p].y + btv.y;
        float base_z = owv[p].z + btv.z;
        float base_w = owv[p].w + btv.w;
        #pragma unroll
        for (int q = 0; q < 4; q++) {
            int j = j0 + tx + 16 * q;
            float4 swv = sw4[b * T + j];
            float2 f0 = unpack2(acc[p][q][0]);
            float2 f1 = unpack2(acc[p][q][1]);
            float2 f2 = unpack2(acc[p][q][2]);
            float2 f3 = unpack2(acc[p][q][3]);
            float4 ev;
            ev.x = __expf(fmaxf(f0.x + f0.y + swv.x + base_x, 0.0f));
            ev.y = __expf(fmaxf(f1.x + f1.y + swv.y + base_y, 0.0f));
            ev.z = __expf(fmaxf(f2.x + f2.y + swv.z + base_z, 0.0f));
            ev.w = __expf(fmaxf(f3.x + f3.y + swv.w + base_w, 0.0f));
            *(float4*)&attn[(((size_t)(b * T + i)) * T + j) * HEADS] = ev;
            ps.x += ev.x; ps.y += ev.y; ps.z += ev.z; ps.w += ev.w;
        }
        #pragma unroll
        for (int m = 8; m >= 1; m >>= 1) {
            ps.x += __shfl_xor_sync(0xffffffffu, ps.x, m);
            ps.y += __shfl_xor_sync(0xffffffffu, ps.y, m);
            ps.z += __shfl_xor_sync(0xffffffffu, ps.z, m);
            ps.w += __shfl_xor_sync(0xffffffffu, ps.w, m);
        }
        if (tx == 0)
            *(float4*)&part[((size_t)(b * T + i) * NJT + jt) * HEADS] = ps;
    }
}

// ---------------------------------------------------------------------------
// Kernel 3b: denominator + normalize + mask; 2 rows per block (shared mask j).
// ---------------------------------------------------------------------------
__global__ void __launch_bounds__(256)
normalize_kernel(const float* __restrict__ part,
                 const int* __restrict__ mask,
                 float* __restrict__ attn) {
    __shared__ float sinv[8];
    const int r = blockIdx.x;          // rows 2r, 2r+1
    const int tid = threadIdx.x;
    const int lane = tid & 31;
    const int wid = tid >> 5;

    if (wid < 2) {
        int row = 2 * r + wid;
        float v = part[row * (NJT * HEADS) + lane];
        v += __shfl_xor_sync(0xffffffffu, v, 4);
        v += __shfl_xor_sync(0xffffffffu, v, 8);
        v += __shfl_xor_sync(0xffffffffu, v, 16);
        if (lane < 4) sinv[wid * 4 + lane] = 1.0f / v;
    }
    __syncthreads();

    const float4 iv0 = make_float4(sinv[0], sinv[1], sinv[2], sinv[3]);
    const float4 iv1 = make_float4(sinv[4], sinv[5], sinv[6], sinv[7]);
    const int bi0 = 2 * r;
    const int b = bi0 >> 9;
    const int mi0 = mask[bi0];
    const int mi1 = mask[bi0 + 1];
    float4* arow0 = (float4*)attn + (size_t)bi0 * T;
    float4* arow1 = arow0 + T;

    #pragma unroll
    for (int rr = 0; rr < 2; rr++) {
        int j = tid + rr * 256;
        int mj = mask[b * T + j];
        float k0 = (mi0 && mj) ? 0.0f : 1.0f;
        float k1 = (mi1 && mj) ? 0.0f : 1.0f;
        float4 v0 = arow0[j];
        float4 v1 = arow1[j];
        v0.x *= iv0.x * k0; v0.y *= iv0.y * k0; v0.z *= iv0.z * k0; v0.w *= iv0.w * k0;
        v1.x *= iv1.x * k1; v1.y *= iv1.y * k1; v1.z *= iv1.z * k1; v1.w *= iv1.w * k1;
        arow0[j] = v0;
        arow1[j] = v1;
    }
}

// ---------------------------------------------------------------------------
extern "C" void kernel_launch(void* const* d_in, const int* in_sizes, int n_in,
                              void* d_out, int out_size) {
    const float* x      = (const float*)d_in[0];
    const float* W_subj = (const float*)d_in[1];
    const float* b_subj = (const float*)d_in[2];
    const float* W_obj  = (const float*)d_in[3];
    const float* b_obj  = (const float*)d_in[4];
    const float* W_t    = (const float*)d_in[5];
    const float* b_t    = (const float*)d_in[6];
    const int*   mask   = (const int*)d_in[7];

    float* out   = (float*)d_out;
    float* xnew  = out;                          // (B,T,2C)
    float* attn  = out + (size_t)M * C2;         // (B,T,T,HEADS)

    float *subj, *obj, *part, *swow;
    cudaGetSymbolAddress((void**)&subj, g_subj);
    cudaGetSymbolAddress((void**)&obj, g_obj);
    cudaGetSymbolAddress((void**)&part, g_part);
    cudaGetSymbolAddress((void**)&swow, g_swow);

    dim3 gg(C / 64, M / 64, 2);   // (4, 32, 2) = 256 blocks
    gemm_kernel<<<gg, 128>>>(x, W_subj, b_subj, W_obj, b_obj, subj, obj, xnew);

    swow_kernel<<<(2 * M) / 4, 128>>>(subj, obj, W_t, swow);

    dim3 ga(T / TJ, T / TI, B);   // (8, 16, 4) = 512 blocks
    rep_exp_kernel<<<ga, 128>>>(subj, obj, W_t, b_t, swow, attn, part);

    normalize_kernel<<<M / 2, 256>>>(part, mask, attn);
}

// round 16
// speedup vs baseline: 1.5379x; 1.0776x over previous
#include <cuda_runtime.h>
#include <cuda_bf16.h>
#include <math.h>
#include <mma.h>

using namespace nvcuda;

// Problem constants
#define B 4
#define T 512
#define C 256
#define C2 512
#define HEADS 4
#define MAXOFF 2
#define M (B * T)      // 2048

#define TI 32          // i-tile per block (rep)
#define TJ 64          // j-tile per block (rep)
#define NJT (T / TJ)   // 8 j-tiles
#define CK 128         // c chunk (rep)

typedef unsigned long long u64;

// Scratch (allocation-free: device globals)
__device__ float g_subj[M * C];
__device__ float g_obj[M * C];
__device__ float g_part[M * NJT * HEADS];       // partial exp-sums per j-tile
__device__ float g_swow[2 * M * HEADS];         // Sw rows 0..M-1, Ow rows M..

// packed f32x2 helpers
static __device__ __forceinline__ u64 fma2(u64 a, u64 b, u64 c) {
    u64 r; asm("fma.rn.f32x2 %0, %1, %2, %3;" : "=l"(r) : "l"(a), "l"(b), "l"(c)); return r;
}
static __device__ __forceinline__ float2 unpack2(u64 v) {
    float2 r; asm("mov.b64 {%0, %1}, %2;" : "=f"(r.x), "=f"(r.y) : "l"(v)); return r;
}
// packed min (FMNMX on ALU pipe); union form lets ptxas pair-allocate
static __device__ __forceinline__ u64 fmin2(u64 a, u64 b) {
    union { u64 v; float2 f; } ua, ub, uc;
    ua.v = a; ub.v = b;
    uc.f.x = fminf(ua.f.x, ub.f.x);
    uc.f.y = fminf(ua.f.y, ub.f.y);
    return uc.v;
}

// ---------------------------------------------------------------------------
// Kernel 1: max-pool along channel (window 5, pad 2) + concat -> x_new
// ---------------------------------------------------------------------------
__global__ void pool_concat_kernel(const float* __restrict__ x,
                                   float* __restrict__ xnew) {
    int idx = blockIdx.x * 256 + threadIdx.x;
    if (idx >= M * C2) return;
    int cc = idx & (C2 - 1);
    int bt = idx >> 9;
    const float* xr = x + bt * C;
    float v;
    if (cc < C) {
        int lo = cc - MAXOFF; if (lo < 0) lo = 0;
        int hi = cc + MAXOFF; if (hi > C - 1) hi = C - 1;
        v = -INFINITY;
        #pragma unroll 5
        for (int c = lo; c <= hi; c++) v = fmaxf(v, xr[c]);
    } else {
        v = xr[cc - C];
    }
    xnew[idx] = v;
}

// ---------------------------------------------------------------------------
// Kernel 2: projection GEMMs on the TENSOR pipe (tf32 wmma, m16n16k8).
// Block tile 64m x 64n, 256 threads = 8 warps (4m x 2n); warp tile 16m x 32n.
// K staged in smem chunks of 32. Epilogue via smem staging + bias (layout-
// agnostic w.r.t. accumulator fragment mapping).
// ---------------------------------------------------------------------------
__global__ void __launch_bounds__(256)
gemm_kernel(const float* __restrict__ A,
            const float* __restrict__ W0,
            const float* __restrict__ b0,
            const float* __restrict__ W1,
            const float* __restrict__ b1,
            float* __restrict__ out0,
            float* __restrict__ out1) {
    __shared__ float As[64 * 36];   // [m][k], stride 36 (144B, 16B-aligned rows)
    __shared__ float Ws[32 * 68];   // [k][n], stride 68 (272B)
    __shared__ float Cs[64 * 68];   // epilogue staging [m][n], stride 68

    const float* W    = blockIdx.z ? W1 : W0;
    const float* bias = blockIdx.z ? b1 : b0;
    float* out        = blockIdx.z ? out1 : out0;

    const int tid = threadIdx.x;
    const int warp = tid >> 5;
    const int wm = warp >> 1;          // 0..3 -> m offset 16*wm
    const int wn = warp & 1;           // 0..1 -> n offset 32*wn
    const int bm = blockIdx.y * 64;
    const int bn = blockIdx.x * 64;

    wmma::fragment<wmma::accumulator, 16, 16, 8, float> c0, c1;
    wmma::fill_fragment(c0, 0.0f);
    wmma::fill_fragment(c1, 0.0f);

    for (int k0 = 0; k0 < C2; k0 += 32) {
        // As: 64m x 32k
        #pragma unroll
        for (int l = 0; l < 2; l++) {
            int t = tid + l * 256;
            int m = t >> 3, kq = t & 7;
            float4 v = *(const float4*)&A[(size_t)(bm + m) * C2 + k0 + 4 * kq];
            *(float4*)&As[m * 36 + 4 * kq] = v;
        }
        // Ws: 32k x 64n
        #pragma unroll
        for (int l = 0; l < 2; l++) {
            int t = tid + l * 256;
            int kw = t >> 4, nq = t & 15;
            float4 v = *(const float4*)&W[(size_t)(k0 + kw) * C + bn + 4 * nq];
            *(float4*)&Ws[kw * 68 + 4 * nq] = v;
        }
        __syncthreads();

        #pragma unroll
        for (int ks = 0; ks < 4; ks++) {
            wmma::fragment<wmma::matrix_a, 16, 16, 8, wmma::precision::tf32,
                           wmma::row_major> a;
            wmma::load_matrix_sync(a, &As[(wm * 16) * 36 + ks * 8], 36);
            #pragma unroll
            for (int i = 0; i < a.num_elements; i++)
                a.x[i] = wmma::__float_to_tf32(a.x[i]);

            wmma::fragment<wmma::matrix_b, 16, 16, 8, wmma::precision::tf32,
                           wmma::row_major> bfr;
            wmma::load_matrix_sync(bfr, &Ws[(ks * 8) * 68 + wn * 32], 68);
            #pragma unroll
            for (int i = 0; i < bfr.num_elements; i++)
                bfr.x[i] = wmma::__float_to_tf32(bfr.x[i]);
            wmma::mma_sync(c0, a, bfr, c0);

            wmma::load_matrix_sync(bfr, &Ws[(ks * 8) * 68 + wn * 32 + 16], 68);
            #pragma unroll
            for (int i = 0; i < bfr.num_elements; i++)
                bfr.x[i] = wmma::__float_to_tf32(bfr.x[i]);
            wmma::mma_sync(c1, a, bfr, c1);
        }
        __syncthreads();
    }

    // Epilogue: fragments -> smem, add bias, coalesced store
    wmma::store_matrix_sync(&Cs[(wm * 16) * 68 + wn * 32], c0, 68,
                            wmma::mem_row_major);
    wmma::store_matrix_sync(&Cs[(wm * 16) * 68 + wn * 32 + 16], c1, 68,
                            wmma::mem_row_major);
    __syncthreads();

    #pragma unroll
    for (int l = 0; l < 4; l++) {
        int t = tid + l * 256;
        int m = t >> 4, nq = t & 15;
        float4 v = *(const float4*)&Cs[m * 68 + 4 * nq];
        float4 bv = *(const float4*)&bias[bn + 4 * nq];
        v.x += bv.x; v.y += bv.y; v.z += bv.z; v.w += bv.w;
        *(float4*)&out[(size_t)(bm + m) * C + bn + 4 * nq] = v;
    }
}

// ---------------------------------------------------------------------------
// Kernel 2b: Sw[j,h] = subj[j,:] @ W_t  and  Ow[i,h] = obj[i,:] @ W_t.
// ---------------------------------------------------------------------------
__global__ void __launch_bounds__(128)
swow_kernel(const float* __restrict__ subj,
            const float* __restrict__ obj,
            const float* __restrict__ W_t,
            float* __restrict__ swow) {
    int gw = (blockIdx.x * 128 + threadIdx.x) >> 5;   // 0..4095
    int lane = threadIdx.x & 31;
    const float* src = (gw < M) ? subj : obj;
    int row = gw & (M - 1);

    float4 a = make_float4(0.f, 0.f, 0.f, 0.f);
    const float4* wt4 = (const float4*)W_t;
    #pragma unroll
    for (int c = lane; c < C; c += 32) {
        float s = src[row * C + c];
        float4 w = wt4[c];
        a.x += s * w.x; a.y += s * w.y; a.z += s * w.z; a.w += s * w.w;
    }
    #pragma unroll
    for (int m = 16; m >= 1; m >>= 1) {
        a.x += __shfl_xor_sync(0xffffffffu, a.x, m);
        a.y += __shfl_xor_sync(0xffffffffu, a.y, m);
        a.z += __shfl_xor_sync(0xffffffffu, a.z, m);
        a.w += __shfl_xor_sync(0xffffffffu, a.w, m);
    }
    if (lane == 0) ((float4*)swow)[gw] = a;
}

// ---------------------------------------------------------------------------
// Kernel 3a (R7/R11 shape): rep = Sw[j]+Ow[i]+b - 2*sum_c min(s,o)*w.
// 128 threads = 16 tx (j, stride-16) x 8 ty (i, stride-8); 4i x 4j x 4h.
// ---------------------------------------------------------------------------
__global__ void __launch_bounds__(128)
rep_exp_kernel(const float* __restrict__ subj,
               const float* __restrict__ obj,
               const float* __restrict__ W_t,
               const float* __restrict__ b_t,
               const float* __restrict__ swow,
               float* __restrict__ attn,
               float* __restrict__ part) {
    __shared__ float s_sh[TJ * CK];     // [jrow][c], swizzled (32KB)
    __shared__ float o_sh[TI * CK];     // [irow][c], swizzled (16KB)
    __shared__ float w_sh[HEADS * C];   // [h][c] = -2*W_t (4KB)

    const int tid = threadIdx.x;
    const int tx = tid & 15;           // j: j0 + tx + 16q
    const int ty = tid >> 4;           // i: i0 + ty + 8p   (0..7)
    const int jt = blockIdx.x;
    const int j0 = jt * TJ;
    const int i0 = blockIdx.y * TI;
    const int b  = blockIdx.z;

    #pragma unroll
    for (int c = tid; c < C; c += 128) {
        float4 wv = *(const float4*)&W_t[c * 4];
        w_sh[0 * C + c] = -2.0f * wv.x;
        w_sh[1 * C + c] = -2.0f * wv.y;
        w_sh[2 * C + c] = -2.0f * wv.z;
        w_sh[3 * C + c] = -2.0f * wv.w;
    }

    u64 acc[4][4][4];
    #pragma unroll
    for (int p = 0; p < 4; p++)
        #pragma unroll
        for (int q = 0; q < 4; q++)
            #pragma unroll
            for (int h = 0; h < 4; h++) acc[p][q][h] = 0ULL;

    const int swj = tx & 7;
    const float* sp[4];
    const float* op[4];
    #pragma unroll
    for (int q = 0; q < 4; q++) sp[q] = s_sh + (tx + 16 * q) * CK;
    #pragma unroll
    for (int p = 0; p < 4; p++) op[p] = o_sh + (ty + 8 * p) * CK;

    for (int ck = 0; ck < C / CK; ck++) {
        const int cbase = ck * CK;
        #pragma unroll
        for (int l = 0; l < 16; l++) {
            int t = tid + l * 128;
            int row = t >> 5;          // 0..63
            int ccg = t & 31;
            int phys = (ccg ^ (row & 7)) << 2;
            float4 sv = *(const float4*)&subj[(b * T + j0 + row) * C + cbase + ccg * 4];
            *(float4*)&s_sh[row * CK + phys] = sv;
        }
        #pragma unroll
        for (int l = 0; l < 8; l++) {
            int t = tid + l * 128;
            int row = t >> 5;          // 0..31
            int ccg = t & 31;
            int phys = (ccg ^ (row & 7)) << 2;
            float4 ov = *(const float4*)&obj[(b * T + i0 + row) * C + cbase + ccg * 4];
            *(float4*)&o_sh[row * CK + phys] = ov;
        }
        __syncthreads();

        const float* wp0 = w_sh + 0 * C + cbase;
        const float* wp1 = w_sh + 1 * C + cbase;
        const float* wp2 = w_sh + 2 * C + cbase;
        const float* wp3 = w_sh + 3 * C + cbase;

        #pragma unroll 1
        for (int g = 0; g < CK / 4; g++) {
            const int gs = ((g ^ swj) << 2);
            const int gi = ((g ^ ty) << 2);
            ulonglong2 S[4], P[4], Wv[4];
            #pragma unroll
            for (int q = 0; q < 4; q++) S[q] = *(const ulonglong2*)(sp[q] + gs);
            #pragma unroll
            for (int p = 0; p < 4; p++) P[p] = *(const ulonglong2*)(op[p] + gi);
            Wv[0] = *(const ulonglong2*)(wp0 + g * 4);
            Wv[1] = *(const ulonglong2*)(wp1 + g * 4);
            Wv[2] = *(const ulonglong2*)(wp2 + g * 4);
            Wv[3] = *(const ulonglong2*)(wp3 + g * 4);

            #pragma unroll
            for (int p = 0; p < 4; p++) {
                #pragma unroll
                for (int q = 0; q < 4; q++) {
                    u64 m0 = fmin2(S[q].x, P[p].x);
                    acc[p][q][0] = fma2(m0, Wv[0].x, acc[p][q][0]);
                    acc[p][q][1] = fma2(m0, Wv[1].x, acc[p][q][1]);
                    acc[p][q][2] = fma2(m0, Wv[2].x, acc[p][q][2]);
                    acc[p][q][3] = fma2(m0, Wv[3].x, acc[p][q][3]);
                    u64 m1 = fmin2(S[q].y, P[p].y);
                    acc[p][q][0] = fma2(m1, Wv[0].y, acc[p][q][0]);
                    acc[p][q][1] = fma2(m1, Wv[1].y, acc[p][q][1]);
                    acc[p][q][2] = fma2(m1, Wv[2].y, acc[p][q][2]);
                    acc[p][q][3] = fma2(m1, Wv[3].y, acc[p][q][3]);
                }
            }
        }
        __syncthreads();
    }

    const float4 btv = *(const float4*)b_t;
    const float4* sw4 = (const float4*)swow;              // rows 0..M-1
    const float4* ow4 = (const float4*)swow + M;          // rows M..

    float4 owv[4];
    #pragma unroll
    for (int p = 0; p < 4; p++) owv[p] = ow4[b * T + i0 + ty + 8 * p];

    #pragma unroll
    for (int p = 0; p < 4; p++) {
        int i = i0 + ty + 8 * p;
        float4 ps = make_float4(0.f, 0.f, 0.f, 0.f);
        float base_x = owv[p].x + btv.x;
        float base_y = owv[p].y + btv.y;
        float base_z = owv[p].z + btv.z;
        float base_w = owv[p].w + btv.w;
        #pragma unroll
        for (int q = 0; q < 4; q++) {
            int j = j0 + tx + 16 * q;
            float4 swv = sw4[b * T + j];
            float2 f0 = unpack2(acc[p][q][0]);
            float2 f1 = unpack2(acc[p][q][1]);
            float2 f2 = unpack2(acc[p][q][2]);
            float2 f3 = unpack2(acc[p][q][3]);
            float4 ev;
            ev.x = __expf(fmaxf(f0.x + f0.y + swv.x + base_x, 0.0f));
            ev.y = __expf(fmaxf(f1.x + f1.y + swv.y + base_y, 0.0f));
            ev.z = __expf(fmaxf(f2.x + f2.y + swv.z + base_z, 0.0f));
            ev.w = __expf(fmaxf(f3.x + f3.y + swv.w + base_w, 0.0f));
            *(float4*)&attn[(((size_t)(b * T + i)) * T + j) * HEADS] = ev;
            ps.x += ev.x; ps.y += ev.y; ps.z += ev.z; ps.w += ev.w;
        }
        #pragma unroll
        for (int m = 8; m >= 1; m >>= 1) {
            ps.x += __shfl_xor_sync(0xffffffffu, ps.x, m);
            ps.y += __shfl_xor_sync(0xffffffffu, ps.y, m);
            ps.z += __shfl_xor_sync(0xffffffffu, ps.z, m);
            ps.w += __shfl_xor_sync(0xffffffffu, ps.w, m);
        }
        if (tx == 0)
            *(float4*)&part[((size_t)(b * T + i) * NJT + jt) * HEADS] = ps;
    }
}

// ---------------------------------------------------------------------------
// Kernel 3b: denominator + normalize + mask; 2 rows per block (shared mask j).
// ---------------------------------------------------------------------------
__global__ void __launch_bounds__(256)
normalize_kernel(const float* __restrict__ part,
                 const int* __restrict__ mask,
                 float* __restrict__ attn) {
    __shared__ float sinv[8];
    const int r = blockIdx.x;          // rows 2r, 2r+1
    const int tid = threadIdx.x;
    const int lane = tid & 31;
    const int wid = tid >> 5;

    if (wid < 2) {
        int row = 2 * r + wid;
        float v = part[row * (NJT * HEADS) + lane];
        v += __shfl_xor_sync(0xffffffffu, v, 4);
        v += __shfl_xor_sync(0xffffffffu, v, 8);
        v += __shfl_xor_sync(0xffffffffu, v, 16);
        if (lane < 4) sinv[wid * 4 + lane] = 1.0f / v;
    }
    __syncthreads();

    const float4 iv0 = make_float4(sinv[0], sinv[1], sinv[2], sinv[3]);
    const float4 iv1 = make_float4(sinv[4], sinv[5], sinv[6], sinv[7]);
    const int bi0 = 2 * r;
    const int b = bi0 >> 9;
    const int mi0 = mask[bi0];
    const int mi1 = mask[bi0 + 1];
    float4* arow0 = (float4*)attn + (size_t)bi0 * T;
    float4* arow1 = arow0 + T;

    #pragma unroll
    for (int rr = 0; rr < 2; rr++) {
        int j = tid + rr * 256;
        int mj = mask[b * T + j];
        float k0 = (mi0 && mj) ? 0.0f : 1.0f;
        float k1 = (mi1 && mj) ? 0.0f : 1.0f;
        float4 v0 = arow0[j];
        float4 v1 = arow1[j];
        v0.x *= iv0.x * k0; v0.y *= iv0.y * k0; v0.z *= iv0.z * k0; v0.w *= iv0.w * k0;
        v1.x *= iv1.x * k1; v1.y *= iv1.y * k1; v1.z *= iv1.z * k1; v1.w *= iv1.w * k1;
        arow0[j] = v0;
        arow1[j] = v1;
    }
}

// ---------------------------------------------------------------------------
extern "C" void kernel_launch(void* const* d_in, const int* in_sizes, int n_in,
                              void* d_out, int out_size) {
    const float* x      = (const float*)d_in[0];
    const float* W_subj = (const float*)d_in[1];
    const float* b_subj = (const float*)d_in[2];
    const float* W_obj  = (const float*)d_in[3];
    const float* b_obj  = (const float*)d_in[4];
    const float* W_t    = (const float*)d_in[5];
    const float* b_t    = (const float*)d_in[6];
    const int*   mask   = (const int*)d_in[7];

    float* out   = (float*)d_out;
    float* xnew  = out;                          // (B,T,2C)
    float* attn  = out + (size_t)M * C2;         // (B,T,T,HEADS)

    float *subj, *obj, *part, *swow;
    cudaGetSymbolAddress((void**)&subj, g_subj);
    cudaGetSymbolAddress((void**)&obj, g_obj);
    cudaGetSymbolAddress((void**)&part, g_part);
    cudaGetSymbolAddress((void**)&swow, g_swow);

    pool_concat_kernel<<<(M * C2 + 255) / 256, 256>>>(x, xnew);

    dim3 gg(C / 64, M / 64, 2);   // (4, 32, 2) = 256 blocks
    gemm_kernel<<<gg, 256>>>(xnew, W_subj, b_subj, W_obj, b_obj, subj, obj);

    swow_kernel<<<(2 * M) / 4, 128>>>(subj, obj, W_t, swow);

    dim3 ga(T / TJ, T / TI, B);   // (8, 16, 4) = 512 blocks
    rep_exp_kernel<<<ga, 128>>>(subj, obj, W_t, b_t, swow, attn, part);

    normalize_kernel<<<M / 2, 256>>>(part, mask, attn);
}